// round 7
// baseline (speedup 1.0000x reference)
#include <cuda_runtime.h>

// ---------------------------------------------------------------------------
// Transformer-XL relative attention.
// Round 5: fast fp32 SGEMM (128x128 tile, BK=8, 8x8 micro, float4, double-buf).
//
// Shapes: BSZ=4, QLEN=1024, KLEN=2048, N_HEAD=16, D_HEAD=64, D_MODEL=1024
// MEM_LEN = 1024. Mask: query i attends to j <= i + 1024.
// rel_shift(BD)[b,i,j] == BD[b,i, j - i + 1023] for all unmasked (i,j).
// ---------------------------------------------------------------------------

#define BSZ 4
#define QLEN 1024
#define KLEN 2048
#define NHEAD 16
#define DHEAD 64
#define DMODEL 1024

// Scratch (allocation-free rule: __device__ globals)
__device__ float g_q [BSZ * QLEN * DMODEL];          // 16 MB
__device__ float g_kv[BSZ * KLEN * 2 * DMODEL];      // 64 MB
__device__ float g_rk[KLEN * DMODEL];                //  8 MB
__device__ float g_av[BSZ * QLEN * DMODEL];          // 16 MB

// ---------------------------------------------------------------------------
// SGEMM: C[M,N] = A[M,K] @ B[K,N]. 128x128 tile, BK=8, 256 thr, 8x8 micro.
// Double-buffered smem, float4 global loads, register prefetch.
// GATHER=1: A row m maps to w row (m/1024)*2048 + 1024 + (m%1024)  (q proj).
// Requires: M%128==0, N%128==0, K%8==0.
// ---------------------------------------------------------------------------
template<int GATHER>
__global__ __launch_bounds__(256) void sgemm128(const float* __restrict__ A,
                                                const float* __restrict__ B,
                                                float* __restrict__ C,
                                                int M, int N, int K)
{
    __shared__ float As[2][8][128];
    __shared__ float Bs[2][8][128];

    const int tid = threadIdx.x;            // 0..255
    const int tx = tid & 15;                // 0..15  (col group)
    const int ty = tid >> 4;                // 0..15  (row group)
    const int bm = blockIdx.y * 128;
    const int bn = blockIdx.x * 128;

    // --- A tile load mapping: 128 rows x 8 k = 1024 floats = 1 float4/thread
    const int am = tid >> 1;                // 0..127 row within tile
    const int ak = (tid & 1) * 4;           // 0 or 4 (k offset)
    long arow;
    {
        int gm = bm + am;
        arow = GATHER ? ((long)(gm >> 10) * KLEN + QLEN + (gm & 1023))
                      : (long)gm;
    }
    const float* Aptr = A + arow * K + ak;

    // --- B tile load mapping: 8 k x 128 n = 1024 floats = 1 float4/thread
    const int bk = tid >> 5;                // 0..7
    const int bnn = (tid & 31) * 4;         // 0..124
    const float* Bptr = B + (long)bk * N + bn + bnn;

    // prologue: load tile 0
    float4 av = *(const float4*)Aptr;
    float4 bv = *(const float4*)Bptr;
    As[0][ak + 0][am] = av.x;
    As[0][ak + 1][am] = av.y;
    As[0][ak + 2][am] = av.z;
    As[0][ak + 3][am] = av.w;
    *(float4*)&Bs[0][bk][bnn] = bv;
    __syncthreads();

    float acc[8][8] = {};
    int buf = 0;

    for (int k0 = 8; k0 <= K; k0 += 8) {
        // prefetch next tile into registers
        if (k0 < K) {
            av = *(const float4*)(Aptr + k0);
            bv = *(const float4*)(Bptr + (long)k0 * N);
        }

        #pragma unroll
        for (int kk = 0; kk < 8; kk++) {
            float4 a0 = *(float4*)&As[buf][kk][ty * 8];
            float4 a1 = *(float4*)&As[buf][kk][ty * 8 + 4];
            float4 b0 = *(float4*)&Bs[buf][kk][tx * 8];
            float4 b1 = *(float4*)&Bs[buf][kk][tx * 8 + 4];
            float a[8] = {a0.x, a0.y, a0.z, a0.w, a1.x, a1.y, a1.z, a1.w};
            float b[8] = {b0.x, b0.y, b0.z, b0.w, b1.x, b1.y, b1.z, b1.w};
            #pragma unroll
            for (int i = 0; i < 8; i++)
                #pragma unroll
                for (int j = 0; j < 8; j++)
                    acc[i][j] += a[i] * b[j];
        }

        if (k0 < K) {
            int nb = buf ^ 1;
            As[nb][ak + 0][am] = av.x;
            As[nb][ak + 1][am] = av.y;
            As[nb][ak + 2][am] = av.z;
            As[nb][ak + 3][am] = av.w;
            *(float4*)&Bs[nb][bk][bnn] = bv;
            __syncthreads();
            buf = nb;
        }
    }

    // writeback: 8 rows x 2 float4
    #pragma unroll
    for (int i = 0; i < 8; i++) {
        float* crow = C + (long)(bm + ty * 8 + i) * N + bn + tx * 8;
        float4 c0 = {acc[i][0], acc[i][1], acc[i][2], acc[i][3]};
        float4 c1 = {acc[i][4], acc[i][5], acc[i][6], acc[i][7]};
        *(float4*)crow = c0;
        *(float4*)(crow + 4) = c1;
    }
}

// ---------------------------------------------------------------------------
// Fused relative attention. grid = (QLEN, NHEAD, BSZ), block = 128 threads.
// ---------------------------------------------------------------------------
__global__ void attn_kernel(const float* __restrict__ rwb,
                            const float* __restrict__ rrb)
{
    __shared__ float s[KLEN];
    __shared__ float qw[DHEAD];
    __shared__ float qr[DHEAD];
    __shared__ float red[128];

    const int i = blockIdx.x;
    const int n = blockIdx.y;
    const int b = blockIdx.z;
    const int tid = threadIdx.x;
    const int count = i + 1025;            // j in [0, i+1024]

    const float* qrow = g_q + (long)(b * QLEN + i) * DMODEL + n * DHEAD;
    if (tid < 64) {
        qw[tid] = qrow[tid] + rwb[n * DHEAD + tid];
    } else {
        int d = tid - 64;
        qr[d] = qrow[d] + rrb[n * DHEAD + d];
    }
    __syncthreads();

    const float scale = 0.125f;

    for (int j = tid; j < count; j += 128) {
        const float* krow  = g_kv + (long)(b * KLEN + j) * (2 * DMODEL) + n * DHEAD;
        const float* rkrow = g_rk + (long)(j - i + 1023) * DMODEL + n * DHEAD;
        float acc = 0.f;
        #pragma unroll
        for (int d = 0; d < DHEAD; d++)
            acc += qw[d] * krow[d] + qr[d] * rkrow[d];
        s[j] = acc * scale;
    }
    __syncthreads();

    float m = -1e30f;
    for (int j = tid; j < count; j += 128) m = fmaxf(m, s[j]);
    red[tid] = m;
    __syncthreads();
    #pragma unroll
    for (int o = 64; o > 0; o >>= 1) {
        if (tid < o) red[tid] = fmaxf(red[tid], red[tid + o]);
        __syncthreads();
    }
    m = red[0];
    __syncthreads();

    float sum = 0.f;
    for (int j = tid; j < count; j += 128) {
        float e = __expf(s[j] - m);
        s[j] = e;
        sum += e;
    }
    red[tid] = sum;
    __syncthreads();
    #pragma unroll
    for (int o = 64; o > 0; o >>= 1) {
        if (tid < o) red[tid] += red[tid + o];
        __syncthreads();
    }
    const float inv = 1.f / red[0];
    __syncthreads();

    const int d = tid & 63;
    const int grp = tid >> 6;
    float acc = 0.f;
    const float* vbase = g_kv + (long)b * KLEN * (2 * DMODEL) + DMODEL + n * DHEAD + d;
    for (int j = grp; j < count; j += 2)
        acc += s[j] * vbase[(long)j * (2 * DMODEL)];
    red[tid] = acc;
    __syncthreads();
    if (tid < 64)
        g_av[(long)(b * QLEN + i) * DMODEL + n * DHEAD + d] =
            (red[tid] + red[tid + 64]) * inv;
}

// ---------------------------------------------------------------------------
extern "C" void kernel_launch(void* const* d_in, const int* in_sizes, int n_in,
                              void* d_out, int out_size)
{
    const float* w   = (const float*)d_in[0];  // [4,2048,1024]
    const float* r   = (const float*)d_in[1];  // [1,2048,1024]
    const float* rwb = (const float*)d_in[2];  // [16,64]
    const float* rrb = (const float*)d_in[3];  // [16,64]
    const float* Wq  = (const float*)d_in[4];  // [1024,1024]
    const float* Wkv = (const float*)d_in[5];  // [1024,2048]
    const float* Wr  = (const float*)d_in[6];  // [1024,1024]
    const float* Wo  = (const float*)d_in[7];  // [1024,1024]
    float* out = (float*)d_out;

    float *q, *kv, *rk, *av;
    cudaGetSymbolAddress((void**)&q,  g_q);
    cudaGetSymbolAddress((void**)&kv, g_kv);
    cudaGetSymbolAddress((void**)&rk, g_rk);
    cudaGetSymbolAddress((void**)&av, g_av);

    const dim3 thr(256);

    // q = w[:, -1024:, :] @ Wq         -> [4096, 1024]
    sgemm128<1><<<dim3(1024 / 128, 4096 / 128), thr>>>(w, Wq, q, 4096, 1024, 1024);
    // kv = w @ Wkv                     -> [8192, 2048]
    sgemm128<0><<<dim3(2048 / 128, 8192 / 128), thr>>>(w, Wkv, kv, 8192, 2048, 1024);
    // rk = r @ Wr                      -> [2048, 1024]
    sgemm128<0><<<dim3(1024 / 128, 2048 / 128), thr>>>(r, Wr, rk, 2048, 1024, 1024);
    // fused relative attention         -> g_av [4096, 1024]
    attn_kernel<<<dim3(QLEN, NHEAD, BSZ), 128>>>(rwb, rrb);
    // out = attn_vec @ Wo              -> [4096, 1024]
    sgemm128<0><<<dim3(1024 / 128, 4096 / 128), thr>>>(av, Wo, out, 4096, 1024, 1024);
}

// round 13
// speedup vs baseline: 1.0218x; 1.0218x over previous
#include <cuda_runtime.h>
#include <cuda_bf16.h>
#include <cstdint>

// ---------------------------------------------------------------------------
// Transformer-XL relative attention — tensor-core GEMMs via mma.sync (bf16
// split precision). tcgen05 is unavailable: the harness build includes a
// plain compute_103 ptxas pass which rejects all sm_103a-only instructions.
// mma.sync.m16n8k16 + ldmatrix are baseline sm_80+ and assemble everywhere.
//
// Shapes: BSZ=4, QLEN=1024, KLEN=2048, N_HEAD=16, D_HEAD=64, D_MODEL=1024
// Mask: query i attends to j <= i + 1024.
// rel_shift(BD)[b,i,j] == BD[b,i, j - i + 1023] for all unmasked (i,j).
//
// GEMM: fp32 X -> (Xh, Xl) bf16 split;  C = Ah*Bh + Ah*Bl + Al*Bh  (fp32 acc)
// error ~2^-17 relative — far under the 1e-3 threshold.
// ---------------------------------------------------------------------------

#define BSZ 4
#define QLEN 1024
#define KLEN 2048
#define NHEAD 16
#define DHEAD 64
#define DMODEL 1024

// fp32 scratch
__device__ float g_q [BSZ * QLEN * DMODEL];
__device__ float g_kv[BSZ * KLEN * 2 * DMODEL];
__device__ float g_rk[KLEN * DMODEL];
__device__ float g_av[BSZ * QLEN * DMODEL];

// bf16 hi/lo operands
__device__ __nv_bfloat16 g_wh [BSZ * KLEN * DMODEL], g_wl [BSZ * KLEN * DMODEL];
__device__ __nv_bfloat16 g_rh [KLEN * DMODEL],       g_rl [KLEN * DMODEL];
__device__ __nv_bfloat16 g_avh[BSZ * QLEN * DMODEL], g_avl[BSZ * QLEN * DMODEL];
__device__ __nv_bfloat16 g_WqTh [DMODEL * DMODEL],     g_WqTl [DMODEL * DMODEL];
__device__ __nv_bfloat16 g_WkvTh[2 * DMODEL * DMODEL], g_WkvTl[2 * DMODEL * DMODEL];
__device__ __nv_bfloat16 g_WrTh [DMODEL * DMODEL],     g_WrTl [DMODEL * DMODEL];
__device__ __nv_bfloat16 g_WoTh [DMODEL * DMODEL],     g_WoTl [DMODEL * DMODEL];

// ---------------------------------------------------------------------------
// PTX helpers (all baseline sm_80+)
// ---------------------------------------------------------------------------
__device__ __forceinline__ uint32_t smem_u32(const void* p) {
    uint32_t a;
    asm("{ .reg .u64 t; cvta.to.shared.u64 t, %1; cvt.u32.u64 %0, t; }"
        : "=r"(a) : "l"(p));
    return a;
}

__device__ __forceinline__ void cp16(uint32_t s, const void* g) {
    asm volatile("cp.async.cg.shared.global [%0], [%1], 16;"
                 :: "r"(s), "l"(g) : "memory");
}
#define CP_COMMIT() asm volatile("cp.async.commit_group;" ::: "memory")
#define CP_WAIT1()  asm volatile("cp.async.wait_group 1;" ::: "memory")
#define CP_WAIT0()  asm volatile("cp.async.wait_group 0;" ::: "memory")

__device__ __forceinline__ void ldsm_x4(uint32_t (&r)[4], uint32_t addr) {
    asm volatile("ldmatrix.sync.aligned.m8n8.x4.shared.b16 {%0,%1,%2,%3}, [%4];"
                 : "=r"(r[0]), "=r"(r[1]), "=r"(r[2]), "=r"(r[3]) : "r"(addr));
}

__device__ __forceinline__ void mma16816(float (&c)[4], const uint32_t (&a)[4],
                                         const uint32_t* b) {
    asm volatile(
        "mma.sync.aligned.m16n8k16.row.col.f32.bf16.bf16.f32 "
        "{%0,%1,%2,%3}, {%4,%5,%6,%7}, {%8,%9}, {%0,%1,%2,%3};"
        : "+f"(c[0]), "+f"(c[1]), "+f"(c[2]), "+f"(c[3])
        : "r"(a[0]), "r"(a[1]), "r"(a[2]), "r"(a[3]), "r"(b[0]), "r"(b[1]));
}

// ---------------------------------------------------------------------------
// GEMM: C[M,N] = (Ah+Al)[M,K] @ (Bh+Bl)^T,  B* stored [N,K] k-major.
// 128x128 CTA tile, 8 warps (2Mx4N), warp 64x32, BK=32, 2-stage cp.async.
// Smem rows padded to 40 bf16 (80B) -> conflict-free ldmatrix.
// GATHER=1: A row m -> (m>>10)*2048 + 1024 + (m&1023)   (q projection).
// ---------------------------------------------------------------------------
#define BK 32
#define ROWPAD 40                         // elements per smem row
#define TILE_E (128 * ROWPAD)             // 5120 bf16 = 10240 B
#define TILE_B (TILE_E * 2)
#define STAGE_B (4 * TILE_B)              // Ah, Al, Bh, Bl
#define GEMM_SMEM (2 * STAGE_B)           // 81920 B

template<int GATHER>
__device__ __forceinline__ void load_stage(
    uint32_t sb, const __nv_bfloat16* Ah, const __nv_bfloat16* Al,
    const __nv_bfloat16* Bh, const __nv_bfloat16* Bl,
    int bm, int bn, int K, int k0, int tid)
{
    #pragma unroll
    for (int i = 0; i < 2; i++) {
        const int q   = tid + i * 256;      // 0..511
        const int row = q >> 2;             // 0..127
        const int cg  = q & 3;              // 16B group
        const uint32_t soff = (uint32_t)(row * ROWPAD + cg * 8) * 2;

        const int gm = bm + row;
        const long arow = GATHER ? ((long)(gm >> 10) * KLEN + QLEN + (gm & 1023))
                                 : (long)gm;
        const long aoff = arow * K + k0 + cg * 8;
        cp16(sb + 0 * TILE_B + soff, Ah + aoff);
        cp16(sb + 1 * TILE_B + soff, Al + aoff);

        const long boff = (long)(bn + row) * K + k0 + cg * 8;
        cp16(sb + 2 * TILE_B + soff, Bh + boff);
        cp16(sb + 3 * TILE_B + soff, Bl + boff);
    }
}

template<int GATHER>
__global__ __launch_bounds__(256) void hmma_gemm(
    const __nv_bfloat16* __restrict__ Ah, const __nv_bfloat16* __restrict__ Al,
    const __nv_bfloat16* __restrict__ Bh, const __nv_bfloat16* __restrict__ Bl,
    float* __restrict__ C, int N, int K)
{
    extern __shared__ __nv_bfloat16 smem[];
    const uint32_t sbase = smem_u32(smem);
    const int tid  = threadIdx.x;
    const int wid  = tid >> 5;
    const int lane = tid & 31;
    const int wm   = wid >> 2;              // 0..1  -> M offset 64*wm
    const int wn   = wid & 3;               // 0..3  -> N offset 32*wn
    const int bm = blockIdx.y * 128;
    const int bn = blockIdx.x * 128;

    float c[4][4][4] = {};                  // [mt][nt][frag]

    const int nchunks = K / BK;

    load_stage<GATHER>(sbase, Ah, Al, Bh, Bl, bm, bn, K, 0, tid);
    CP_COMMIT();

    for (int ch = 0; ch < nchunks; ch++) {
        if (ch + 1 < nchunks) {
            load_stage<GATHER>(sbase + ((ch + 1) & 1) * STAGE_B,
                               Ah, Al, Bh, Bl, bm, bn, K, (ch + 1) * BK, tid);
            CP_COMMIT();
            CP_WAIT1();
        } else {
            CP_WAIT0();
        }
        __syncthreads();

        const uint32_t st = sbase + (ch & 1) * STAGE_B;
        const uint32_t sAh = st, sAl = st + TILE_B;
        const uint32_t sBh = st + 2 * TILE_B, sBl = st + 3 * TILE_B;

        #pragma unroll
        for (int ks = 0; ks < 2; ks++) {
            // ---- A fragments: addr = (row, col) row-major ----------------
            const uint32_t arow = wm * 64 + (lane & 15);
            const uint32_t acol = ks * 16 + (lane >> 4) * 8;
            uint32_t ah[4][4], al[4][4];
            #pragma unroll
            for (int mt = 0; mt < 4; mt++) {
                const uint32_t o = ((arow + mt * 16) * ROWPAD + acol) * 2;
                ldsm_x4(ah[mt], sAh + o);
                ldsm_x4(al[mt], sAl + o);
            }
            // ---- B fragments: rows = n, cols = k -------------------------
            const uint32_t brow = wn * 32 + (lane >> 4) * 8 + (lane & 7);
            const uint32_t bcol = ks * 16 + ((lane >> 3) & 1) * 8;
            uint32_t bh[2][4], bl[2][4];    // [nt2][{nt even b0,b1, nt odd b0,b1}]
            #pragma unroll
            for (int nt2 = 0; nt2 < 2; nt2++) {
                const uint32_t o = ((brow + nt2 * 16) * ROWPAD + bcol) * 2;
                ldsm_x4(bh[nt2], sBh + o);
                ldsm_x4(bl[nt2], sBl + o);
            }
            // ---- 48 MMAs: AhBh + AhBl + AlBh -----------------------------
            #pragma unroll
            for (int mt = 0; mt < 4; mt++) {
                #pragma unroll
                for (int nt = 0; nt < 4; nt++) {
                    const uint32_t* pbh = &bh[nt >> 1][(nt & 1) * 2];
                    const uint32_t* pbl = &bl[nt >> 1][(nt & 1) * 2];
                    mma16816(c[mt][nt], ah[mt], pbh);
                    mma16816(c[mt][nt], ah[mt], pbl);
                    mma16816(c[mt][nt], al[mt], pbh);
                }
            }
        }
        __syncthreads();
    }

    // ---- epilogue: c frag (row=g, col=2*tg) / (row=g+8) -------------------
    const int g  = lane >> 2;
    const int tg = lane & 3;
    #pragma unroll
    for (int mt = 0; mt < 4; mt++) {
        #pragma unroll
        for (int nt = 0; nt < 4; nt++) {
            const int m = bm + wm * 64 + mt * 16 + g;
            const int n = bn + wn * 32 + nt * 8 + 2 * tg;
            *(float2*)(C + (long)m * N + n)       = make_float2(c[mt][nt][0], c[mt][nt][1]);
            *(float2*)(C + (long)(m + 8) * N + n) = make_float2(c[mt][nt][2], c[mt][nt][3]);
        }
    }
}

// ---------------------------------------------------------------------------
// fp32 -> (hi, lo) bf16 split, vectorized by 4.
// ---------------------------------------------------------------------------
__global__ void cvt_split(const float* __restrict__ in,
                          __nv_bfloat16* __restrict__ h,
                          __nv_bfloat16* __restrict__ l, int n4)
{
    int i = blockIdx.x * 256 + threadIdx.x;
    if (i >= n4) return;
    float4 v = ((const float4*)in)[i];
    __nv_bfloat16 h0 = __float2bfloat16(v.x);
    __nv_bfloat16 h1 = __float2bfloat16(v.y);
    __nv_bfloat16 h2 = __float2bfloat16(v.z);
    __nv_bfloat16 h3 = __float2bfloat16(v.w);
    __nv_bfloat162* H = (__nv_bfloat162*)h;
    __nv_bfloat162* L = (__nv_bfloat162*)l;
    H[2 * i + 0] = __nv_bfloat162(h0, h1);
    H[2 * i + 1] = __nv_bfloat162(h2, h3);
    L[2 * i + 0] = __nv_bfloat162(__float2bfloat16(v.x - __bfloat162float(h0)),
                                  __float2bfloat16(v.y - __bfloat162float(h1)));
    L[2 * i + 1] = __nv_bfloat162(__float2bfloat16(v.z - __bfloat162float(h2)),
                                  __float2bfloat16(v.w - __bfloat162float(h3)));
}

// ---------------------------------------------------------------------------
// W[K,N] fp32 -> T[N,K] bf16 hi/lo (transpose + split). block (32,8).
// ---------------------------------------------------------------------------
__global__ void transpose_split(const float* __restrict__ W,
                                __nv_bfloat16* __restrict__ Th,
                                __nv_bfloat16* __restrict__ Tl,
                                int Kdim, int Ndim)
{
    __shared__ float t[32][33];
    const int bx = blockIdx.x * 32;   // N base
    const int by = blockIdx.y * 32;   // K base
    const int tx = threadIdx.x;

    #pragma unroll
    for (int i = threadIdx.y; i < 32; i += 8)
        t[i][tx] = W[(long)(by + i) * Ndim + bx + tx];
    __syncthreads();

    #pragma unroll
    for (int i = threadIdx.y; i < 32; i += 8) {
        const float v = t[tx][i];
        const long o = (long)(bx + i) * Kdim + by + tx;
        const __nv_bfloat16 hv = __float2bfloat16(v);
        Th[o] = hv;
        Tl[o] = __float2bfloat16(v - __bfloat162float(hv));
    }
}

// ---------------------------------------------------------------------------
// Fused relative attention (unchanged). grid = (QLEN, NHEAD, BSZ), 128 thr.
// ---------------------------------------------------------------------------
__global__ void attn_kernel(const float* __restrict__ rwb,
                            const float* __restrict__ rrb)
{
    __shared__ float s[KLEN];
    __shared__ float qw[DHEAD];
    __shared__ float qr[DHEAD];
    __shared__ float red[128];

    const int i = blockIdx.x;
    const int n = blockIdx.y;
    const int b = blockIdx.z;
    const int tid = threadIdx.x;
    const int count = i + 1025;

    const float* qrow = g_q + (long)(b * QLEN + i) * DMODEL + n * DHEAD;
    if (tid < 64) {
        qw[tid] = qrow[tid] + rwb[n * DHEAD + tid];
    } else {
        int d = tid - 64;
        qr[d] = qrow[d] + rrb[n * DHEAD + d];
    }
    __syncthreads();

    const float scale = 0.125f;

    for (int j = tid; j < count; j += 128) {
        const float* krow  = g_kv + (long)(b * KLEN + j) * (2 * DMODEL) + n * DHEAD;
        const float* rkrow = g_rk + (long)(j - i + 1023) * DMODEL + n * DHEAD;
        float acc = 0.f;
        #pragma unroll
        for (int d = 0; d < DHEAD; d++)
            acc += qw[d] * krow[d] + qr[d] * rkrow[d];
        s[j] = acc * scale;
    }
    __syncthreads();

    float m = -1e30f;
    for (int j = tid; j < count; j += 128) m = fmaxf(m, s[j]);
    red[tid] = m;
    __syncthreads();
    #pragma unroll
    for (int o = 64; o > 0; o >>= 1) {
        if (tid < o) red[tid] = fmaxf(red[tid], red[tid + o]);
        __syncthreads();
    }
    m = red[0];
    __syncthreads();

    float sum = 0.f;
    for (int j = tid; j < count; j += 128) {
        float e = __expf(s[j] - m);
        s[j] = e;
        sum += e;
    }
    red[tid] = sum;
    __syncthreads();
    #pragma unroll
    for (int o = 64; o > 0; o >>= 1) {
        if (tid < o) red[tid] += red[tid + o];
        __syncthreads();
    }
    const float inv = 1.f / red[0];
    __syncthreads();

    const int d = tid & 63;
    const int grp = tid >> 6;
    float acc = 0.f;
    const float* vbase = g_kv + (long)b * KLEN * (2 * DMODEL) + DMODEL + n * DHEAD + d;
    for (int j = grp; j < count; j += 2)
        acc += s[j] * vbase[(long)j * (2 * DMODEL)];
    red[tid] = acc;
    __syncthreads();
    if (tid < 64)
        g_av[(long)(b * QLEN + i) * DMODEL + n * DHEAD + d] =
            (red[tid] + red[tid + 64]) * inv;
}

// ---------------------------------------------------------------------------
extern "C" void kernel_launch(void* const* d_in, const int* in_sizes, int n_in,
                              void* d_out, int out_size)
{
    const float* w   = (const float*)d_in[0];  // [4,2048,1024]
    const float* r   = (const float*)d_in[1];  // [1,2048,1024]
    const float* rwb = (const float*)d_in[2];
    const float* rrb = (const float*)d_in[3];
    const float* Wq  = (const float*)d_in[4];  // [1024,1024]
    const float* Wkv = (const float*)d_in[5];  // [1024,2048]
    const float* Wr  = (const float*)d_in[6];  // [1024,1024]
    const float* Wo  = (const float*)d_in[7];  // [1024,1024]
    float* out = (float*)d_out;

    float *q, *kv, *rk, *av;
    cudaGetSymbolAddress((void**)&q,  g_q);
    cudaGetSymbolAddress((void**)&kv, g_kv);
    cudaGetSymbolAddress((void**)&rk, g_rk);
    cudaGetSymbolAddress((void**)&av, g_av);

    __nv_bfloat16 *wh, *wl, *rh, *rl, *avh, *avl;
    __nv_bfloat16 *WqTh, *WqTl, *WkvTh, *WkvTl, *WrTh, *WrTl, *WoTh, *WoTl;
    cudaGetSymbolAddress((void**)&wh,  g_wh);   cudaGetSymbolAddress((void**)&wl,  g_wl);
    cudaGetSymbolAddress((void**)&rh,  g_rh);   cudaGetSymbolAddress((void**)&rl,  g_rl);
    cudaGetSymbolAddress((void**)&avh, g_avh);  cudaGetSymbolAddress((void**)&avl, g_avl);
    cudaGetSymbolAddress((void**)&WqTh,  g_WqTh);  cudaGetSymbolAddress((void**)&WqTl,  g_WqTl);
    cudaGetSymbolAddress((void**)&WkvTh, g_WkvTh); cudaGetSymbolAddress((void**)&WkvTl, g_WkvTl);
    cudaGetSymbolAddress((void**)&WrTh,  g_WrTh);  cudaGetSymbolAddress((void**)&WrTl,  g_WrTl);
    cudaGetSymbolAddress((void**)&WoTh,  g_WoTh);  cudaGetSymbolAddress((void**)&WoTl,  g_WoTl);

    cudaFuncSetAttribute(hmma_gemm<0>, cudaFuncAttributeMaxDynamicSharedMemorySize, GEMM_SMEM);
    cudaFuncSetAttribute(hmma_gemm<1>, cudaFuncAttributeMaxDynamicSharedMemorySize, GEMM_SMEM);

    // --- splits & weight transposes ---
    cvt_split<<<(BSZ * KLEN * DMODEL / 4 + 255) / 256, 256>>>(w, wh, wl, BSZ * KLEN * DMODEL / 4);
    cvt_split<<<(KLEN * DMODEL / 4 + 255) / 256, 256>>>(r, rh, rl, KLEN * DMODEL / 4);
    transpose_split<<<dim3(DMODEL / 32, DMODEL / 32),     dim3(32, 8)>>>(Wq,  WqTh,  WqTl,  DMODEL, DMODEL);
    transpose_split<<<dim3(2 * DMODEL / 32, DMODEL / 32), dim3(32, 8)>>>(Wkv, WkvTh, WkvTl, DMODEL, 2 * DMODEL);
    transpose_split<<<dim3(DMODEL / 32, DMODEL / 32),     dim3(32, 8)>>>(Wr,  WrTh,  WrTl,  DMODEL, DMODEL);
    transpose_split<<<dim3(DMODEL / 32, DMODEL / 32),     dim3(32, 8)>>>(Wo,  WoTh,  WoTl,  DMODEL, DMODEL);

    // --- projections (tensor core) ---
    // q = w_tail @ Wq   [4096 x 1024]
    hmma_gemm<1><<<dim3(1024 / 128, 4096 / 128), 256, GEMM_SMEM>>>(wh, wl, WqTh, WqTl, q, 1024, DMODEL);
    // kv = w @ Wkv      [8192 x 2048]
    hmma_gemm<0><<<dim3(2048 / 128, 8192 / 128), 256, GEMM_SMEM>>>(wh, wl, WkvTh, WkvTl, kv, 2048, DMODEL);
    // rk = r @ Wr       [2048 x 1024]
    hmma_gemm<0><<<dim3(1024 / 128, 2048 / 128), 256, GEMM_SMEM>>>(rh, rl, WrTh, WrTl, rk, 1024, DMODEL);

    // --- attention ---
    attn_kernel<<<dim3(QLEN, NHEAD, BSZ), 128>>>(rwb, rrb);

    // --- output projection ---
    cvt_split<<<(BSZ * QLEN * DMODEL / 4 + 255) / 256, 256>>>(av, avh, avl, BSZ * QLEN * DMODEL / 4);
    hmma_gemm<0><<<dim3(1024 / 128, 4096 / 128), 256, GEMM_SMEM>>>(avh, avl, WoTh, WoTl, out, 1024, DMODEL);
}